// round 1
// baseline (speedup 1.0000x reference)
#include <cuda_runtime.h>
#include <cuda_bf16.h>

#define BB 32
#define TT 36
#define NN 10000
#define FF 3
#define RR 20
#define HH 10
#define PRED_ELEMS (BB*HH*NN)   // 3,200,000
#define REG_ELEMS  (BB*HH*RR)   // 6,400

// Scratch (device globals — no allocation allowed)
__device__ float g_tm[BB*NN];       // time_mean[b, n]
__device__ float g_rsum[BB*RR];
__device__ float g_rcnt[BB*RR];
__device__ float g_g1;
__device__ int   g_is64;

// ---------------------------------------------------------------------------
// Detect whether cluster_id is int64 or int32. For int64 little-endian small
// positive values, every odd 32-bit word is 0 and even words are < 64. For
// int32 data (values uniform in [0,20)), 128 consecutive odd words being all
// zero has probability ~20^-128.
__global__ void k_detect(const int* __restrict__ cid) {
    if (threadIdx.x == 0 && blockIdx.x == 0) {
        int is64 = 1;
        for (int k = 0; k < 128; k++) {
            int lo = cid[2*k], hi = cid[2*k + 1];
            if (hi != 0 || (unsigned)lo >= 64u) { is64 = 0; break; }
        }
        g_is64 = is64;
    }
}

// ---------------------------------------------------------------------------
// Main HBM-bound pass: NaN-aware mean over T for channel 0.
// Each thread owns 4 consecutive nodes => 12 consecutive floats per t,
// loaded as 3 aligned float4. Channel-0 values sit at lanes 0,3,6,9.
__global__ void k_time_mean(const float* __restrict__ seq) {
    const int perB = NN / 4;                 // 2500
    int tid = blockIdx.x * blockDim.x + threadIdx.x;
    if (tid >= BB * perB) return;
    int b  = tid / perB;
    int n0 = (tid - b * perB) * 4;

    float s0 = 0.f, s1 = 0.f, s2 = 0.f, s3 = 0.f;
    float c0 = 0.f, c1 = 0.f, c2 = 0.f, c3 = 0.f;

#pragma unroll 6
    for (int t = 0; t < TT; t++) {
        size_t off = ((size_t)(b * TT + t) * NN + n0) * FF;
        float4 v0 = __ldg((const float4*)(seq + off));
        float4 v1 = __ldg((const float4*)(seq + off + 4));
        float4 v2 = __ldg((const float4*)(seq + off + 8));
        float a0 = v0.x, a1 = v0.w, a2 = v1.z, a3 = v2.y;
        if (a0 == a0) { s0 += a0; c0 += 1.f; }
        if (a1 == a1) { s1 += a1; c1 += 1.f; }
        if (a2 == a2) { s2 += a2; c2 += 1.f; }
        if (a3 == a3) { s3 += a3; c3 += 1.f; }
    }
    float4 r;
    r.x = s0 / c0;   // 0/0 -> NaN matches reference all-NaN-node semantics
    r.y = s1 / c1;
    r.z = s2 / c2;
    r.w = s3 / c3;
    *(float4*)(g_tm + (size_t)b * NN + n0) = r;
}

// ---------------------------------------------------------------------------
// Per-(b, region) NaN-aware sums. One block per b, one warp per region.
// Warp-shuffle reduction => deterministic.
__global__ void k_region(const void* __restrict__ cid_raw) {
    int b    = blockIdx.x;
    int r    = threadIdx.x >> 5;
    int lane = threadIdx.x & 31;
    const bool is64 = (g_is64 != 0);
    const long long* c64 = (const long long*)cid_raw;
    const int*       c32 = (const int*)cid_raw;
    const float* tm = g_tm + (size_t)b * NN;

    float s = 0.f, c = 0.f;
    for (int n = lane; n < NN; n += 32) {
        int cv = is64 ? (int)c64[n] : c32[n];
        if (cv == r) {
            float v = tm[n];
            if (v == v) { s += v; c += 1.f; }
        }
    }
#pragma unroll
    for (int o = 16; o > 0; o >>= 1) {
        s += __shfl_down_sync(0xffffffffu, s, o);
        c += __shfl_down_sync(0xffffffffu, c, o);
    }
    if (lane == 0) {
        g_rsum[b * RR + r] = s;
        g_rcnt[b * RR + r] = c;
    }
}

// ---------------------------------------------------------------------------
// Single-block finalize: global means g1/g2 (deterministic shared-mem tree),
// write the 6400 regional outputs, stash g1 for k_pred.
__global__ void k_small(float* __restrict__ out) {
    __shared__ float sh0[256], sh1[256], sh2[256], sh3[256];
    int t = threadIdx.x;
    float ts = 0.f, tc = 0.f, ms = 0.f, mc = 0.f;
    for (int i = t; i < BB * RR; i += 256) {
        float s = g_rsum[i], c = g_rcnt[i];
        ts += s; tc += c;
        if (c > 0.f) { ms += s / c; mc += 1.f; }
    }
    sh0[t] = ts; sh1[t] = tc; sh2[t] = ms; sh3[t] = mc;
    __syncthreads();
#pragma unroll
    for (int o = 128; o > 0; o >>= 1) {
        if (t < o) {
            sh0[t] += sh0[t + o];
            sh1[t] += sh1[t + o];
            sh2[t] += sh2[t + o];
            sh3[t] += sh3[t + o];
        }
        __syncthreads();
    }
    // g1: regions partition nodes, so sum over (b,r) rsum == sum over valid
    // time_means; H-tiling cancels in numerator and denominator.
    float g1 = sh0[0] / sh1[0];
    float g2 = sh2[0] / sh3[0];
    if (t == 0) g_g1 = g1;

    // regional output: [B, H, R], value independent of h
    for (int i = t; i < REG_ELEMS; i += 256) {
        int b  = i / (HH * RR);
        int rr = i % RR;
        float c = g_rcnt[b * RR + rr];
        float v = (c > 0.f) ? (g_rsum[b * RR + rr] / c) : g2;
        out[PRED_ELEMS + i] = v;
    }
}

// ---------------------------------------------------------------------------
// Write the 3.2M pred outputs: tile time_mean over H, NaN -> g1. float4 I/O.
__global__ void k_pred(float* __restrict__ out) {
    int j = blockIdx.x * blockDim.x + threadIdx.x;   // float4 index
    if (j >= PRED_ELEMS / 4) return;
    int flat = j * 4;
    int b = flat / (HH * NN);
    int n = flat % NN;                                // NN % 4 == 0 -> aligned
    float g1 = g_g1;
    float4 v = *(const float4*)(g_tm + (size_t)b * NN + n);
    v.x = (v.x == v.x) ? v.x : g1;
    v.y = (v.y == v.y) ? v.y : g1;
    v.z = (v.z == v.z) ? v.z : g1;
    v.w = (v.w == v.w) ? v.w : g1;
    ((float4*)out)[j] = v;
}

// ---------------------------------------------------------------------------
extern "C" void kernel_launch(void* const* d_in, const int* in_sizes, int n_in,
                              void* d_out, int out_size) {
    const float* seq = (const float*)d_in[0];
    const void*  cid = d_in[1];
    float* out = (float*)d_out;

    k_detect<<<1, 32>>>((const int*)cid);
    {
        int threads = BB * (NN / 4);                  // 80,000
        k_time_mean<<<(threads + 255) / 256, 256>>>(seq);
    }
    k_region<<<BB, RR * 32>>>(cid);
    k_small<<<1, 256>>>(out);
    k_pred<<<(PRED_ELEMS / 4 + 255) / 256, 256>>>(out);
}

// round 2
// speedup vs baseline: 1.7330x; 1.7330x over previous
#include <cuda_runtime.h>
#include <cuda_bf16.h>

#define BB 32
#define TT 36
#define NN 10000
#define FF 3
#define RR 20
#define HH 10
#define CHUNKS 10                 // blocks per batch; 1000 nodes per chunk
#define NODES_PER_CHUNK (NN / CHUNKS)       // 1000
#define ACTIVE_THREADS (NODES_PER_CHUNK/4)  // 250 threads own 4 nodes each
#define PRED_ELEMS (BB*HH*NN)     // 3,200,000
#define REG_ELEMS  (BB*HH*RR)     // 6,400
#define NAN_CAP    (BB*NN)

// Scratch (device globals — no allocation allowed)
__device__ float g_ps[BB][CHUNKS][RR];   // partial region sums
__device__ float g_pc[BB][CHUNKS][RR];   // partial region counts
__device__ int   g_nan_count = 0;
__device__ int   g_nan_list[NAN_CAP];

// ---------------------------------------------------------------------------
// Kernel A: everything heavy, one pass over seq.
//  grid = (CHUNKS, BB), block = 256 (250 active for node work)
__global__ void __launch_bounds__(256) k_main(const float* __restrict__ seq,
                                              const void* __restrict__ cid_raw,
                                              float* __restrict__ out) {
    const int tid   = threadIdx.x;
    const int lane  = tid & 31;
    const int warp  = tid >> 5;
    const int chunk = blockIdx.x;
    const int b     = blockIdx.y;

    __shared__ int   s_is64;
    __shared__ float s_rs[8][RR];
    __shared__ float s_rc[8][RR];

    // --- dtype detect: warp 0, fully parallel loads, ballot AND ---
    if (warp == 0) {
        const int* c32 = (const int*)cid_raw;
        int ok = 1;
        #pragma unroll
        for (int k = 0; k < 4; k++) {           // lane*4+k -> 128 id slots
            int idx = (lane * 4 + k) * 2;       // int64 word pair
            int lo = c32[idx], hi = c32[idx + 1];
            if (hi != 0 || (unsigned)lo >= 64u) ok = 0;
        }
        unsigned bal = __ballot_sync(0xffffffffu, ok);
        if (lane == 0) s_is64 = (bal == 0xffffffffu);
    }

    // --- NaN-aware time mean over T for 4 consecutive nodes ---
    const bool active = (tid < ACTIVE_THREADS);
    const int n0 = chunk * NODES_PER_CHUNK + tid * 4;   // valid iff active

    float s0=0.f,s1=0.f,s2=0.f,s3=0.f;
    float c0=0.f,c1=0.f,c2=0.f,c3=0.f;

    if (active) {
        const float* base = seq + ((size_t)b * TT * NN + n0) * FF;
        #pragma unroll 6
        for (int t = 0; t < TT; t++) {
            const float* p = base + (size_t)t * (NN * FF);
            float4 v0 = __ldg((const float4*)(p));
            float4 v1 = __ldg((const float4*)(p + 4));
            float4 v2 = __ldg((const float4*)(p + 8));
            float a0 = v0.x, a1 = v0.w, a2 = v1.z, a3 = v2.y;
            if (a0 == a0) { s0 += a0; c0 += 1.f; }
            if (a1 == a1) { s1 += a1; c1 += 1.f; }
            if (a2 == a2) { s2 += a2; c2 += 1.f; }
            if (a3 == a3) { s3 += a3; c3 += 1.f; }
        }
    }

    float m0 = s0/c0, m1 = s1/c1, m2 = s2/c2, m3 = s3/c3;  // 0/0 -> NaN

    // --- write pred output tiled over H (NaNs fixed later by k_fin) ---
    if (active) {
        float4 r; r.x = m0; r.y = m1; r.z = m2; r.w = m3;
        float* ob = out + (size_t)b * (HH * NN) + n0;
        #pragma unroll
        for (int h = 0; h < HH; h++)
            *(float4*)(ob + h * NN) = r;

        // record all-NaN nodes (expected never: 0.05^36)
        if (c0 == 0.f) { int i = atomicAdd(&g_nan_count, 1); if (i < NAN_CAP) g_nan_list[i] = b * NN + n0;     }
        if (c1 == 0.f) { int i = atomicAdd(&g_nan_count, 1); if (i < NAN_CAP) g_nan_list[i] = b * NN + n0 + 1; }
        if (c2 == 0.f) { int i = atomicAdd(&g_nan_count, 1); if (i < NAN_CAP) g_nan_list[i] = b * NN + n0 + 2; }
        if (c3 == 0.f) { int i = atomicAdd(&g_nan_count, 1); if (i < NAN_CAP) g_nan_list[i] = b * NN + n0 + 3; }
    }

    __syncthreads();   // s_is64 ready

    // --- load cluster ids for the 4 nodes ---
    int r0=-1, r1=-1, r2=-1, r3=-1;
    if (active) {
        if (s_is64) {
            const long long* c64 = (const long long*)cid_raw;
            r0=(int)c64[n0]; r1=(int)c64[n0+1]; r2=(int)c64[n0+2]; r3=(int)c64[n0+3];
        } else {
            const int* c32 = (const int*)cid_raw;
            int4 cv = __ldg((const int4*)(c32 + n0));
            r0=cv.x; r1=cv.y; r2=cv.z; r3=cv.w;
        }
    }
    // valid-masked values for region sums
    float v0 = (c0>0.f)?m0:0.f, v1 = (c1>0.f)?m1:0.f;
    float v2 = (c2>0.f)?m2:0.f, v3 = (c3>0.f)?m3:0.f;
    float k0 = (c0>0.f)?1.f:0.f, k1 = (c1>0.f)?1.f:0.f;
    float k2 = (c2>0.f)?1.f:0.f, k3 = (c3>0.f)?1.f:0.f;

    // --- per-warp region reduction (deterministic shuffles) ---
    #pragma unroll
    for (int r = 0; r < RR; r++) {
        float s = 0.f, c = 0.f;
        if (r0 == r) { s += v0; c += k0; }
        if (r1 == r) { s += v1; c += k1; }
        if (r2 == r) { s += v2; c += k2; }
        if (r3 == r) { s += v3; c += k3; }
        #pragma unroll
        for (int o = 16; o > 0; o >>= 1) {
            s += __shfl_xor_sync(0xffffffffu, s, o);
            c += __shfl_xor_sync(0xffffffffu, c, o);
        }
        if (lane == 0) { s_rs[warp][r] = s; s_rc[warp][r] = c; }
    }
    __syncthreads();

    // --- cross-warp reduce (fixed order) + global partial write ---
    if (tid < RR) {
        float s = 0.f, c = 0.f;
        #pragma unroll
        for (int w = 0; w < 8; w++) { s += s_rs[w][tid]; c += s_rc[w][tid]; }
        g_ps[b][chunk][tid] = s;
        g_pc[b][chunk][tid] = c;
    }
}

// ---------------------------------------------------------------------------
// Kernel B: finalize. 1 block, 256 threads.
__global__ void k_fin(float* __restrict__ out) {
    __shared__ float s_rsum[BB*RR];
    __shared__ float s_rcnt[BB*RR];
    __shared__ float sh0[256], sh1[256], sh2[256], sh3[256];
    const int t = threadIdx.x;

    // reduce chunk partials (fixed order) -> per (b, r)
    for (int i = t; i < BB*RR; i += 256) {
        int b = i / RR, r = i % RR;
        float s = 0.f, c = 0.f;
        #pragma unroll
        for (int ch = 0; ch < CHUNKS; ch++) { s += g_ps[b][ch][r]; c += g_pc[b][ch][r]; }
        s_rsum[i] = s; s_rcnt[i] = c;
    }
    __syncthreads();

    // global reductions: g1 = total_sum/total_cnt (regions partition nodes,
    // H-tiling cancels); g2 = mean of valid region-means
    float ts=0.f, tc=0.f, ms=0.f, mc=0.f;
    for (int i = t; i < BB*RR; i += 256) {
        float s = s_rsum[i], c = s_rcnt[i];
        ts += s; tc += c;
        if (c > 0.f) { ms += s / c; mc += 1.f; }
    }
    sh0[t]=ts; sh1[t]=tc; sh2[t]=ms; sh3[t]=mc;
    __syncthreads();
    #pragma unroll
    for (int o = 128; o > 0; o >>= 1) {
        if (t < o) { sh0[t]+=sh0[t+o]; sh1[t]+=sh1[t+o]; sh2[t]+=sh2[t+o]; sh3[t]+=sh3[t+o]; }
        __syncthreads();
    }
    const float g1 = sh0[0] / sh1[0];
    const float g2 = sh2[0] / sh3[0];

    // regional output [B, H, R] (independent of h)
    for (int i = t; i < REG_ELEMS; i += 256) {
        int b = i / (HH * RR);
        int r = i % RR;
        float c = s_rcnt[b * RR + r];
        out[PRED_ELEMS + i] = (c > 0.f) ? (s_rsum[b * RR + r] / c) : g2;
    }

    // NaN fixup in pred output (expected 0 entries)
    int cnt = g_nan_count;
    if (cnt > NAN_CAP) cnt = NAN_CAP;
    for (int i = t; i < cnt; i += 256) {
        int code = g_nan_list[i];
        int b = code / NN, n = code % NN;
        float* ob = out + (size_t)b * (HH * NN) + n;
        #pragma unroll
        for (int h = 0; h < HH; h++) ob[h * NN] = g1;
    }
    __syncthreads();
    if (t == 0) g_nan_count = 0;   // reset for next graph replay
}

// ---------------------------------------------------------------------------
extern "C" void kernel_launch(void* const* d_in, const int* in_sizes, int n_in,
                              void* d_out, int out_size) {
    const float* seq = (const float*)d_in[0];
    const void*  cid = d_in[1];
    float* out = (float*)d_out;

    dim3 grid(CHUNKS, BB);
    k_main<<<grid, 256>>>(seq, cid, out);
    k_fin<<<1, 256>>>(out);
}